// round 1
// baseline (speedup 1.0000x reference)
#include <cuda_runtime.h>

#define BATCH 256
#define D     512
#define HID   2048
#define SLOTS 32768
#define NSPLIT 16

#define NEG_INF (-1e30f)

// ---------------- device scratch (static allocation only) ----------------
__device__ float g_K[BATCH * D];
__device__ float g_V[BATCH * D];
__device__ float g_G[BATCH * BATCH];
__device__ float g_Sb[(size_t)BATCH * SLOTS];   // raw scores, then P = exp(. - c) in-place
__device__ float g_c[BATCH];
__device__ float g_E[BATCH];
__device__ float g_t1v[BATCH];
__device__ float g_t2v[BATCH];
__device__ int   g_t1i[BATCH];
__device__ int   g_t2i[BATCH];
__device__ int   g_slot[BATCH];
__device__ int   g_death[BATCH];
__device__ float g_A1[BATCH * BATCH];
__device__ float g_A2[BATCH * BATCH];
__device__ float g_Rpart[(size_t)NSPLIT * BATCH * D];
__device__ float g_merged[BATCH * 2 * D];
__device__ float g_hidden[BATCH * HID];

// ---------------- generic fp32 GEMM, C[M,N] = A[M,K] @ B[N,K]^T (+bias)(+relu) ----
__global__ __launch_bounds__(256) void gemm_nt(
    const float* __restrict__ A, const float* __restrict__ B,
    const float* __restrict__ bias, float* __restrict__ C,
    int M, int N, int K, int relu)
{
    __shared__ float As[16][64];
    __shared__ float Bs[16][64];
    const int bm = blockIdx.y * 64;
    const int bn = blockIdx.x * 64;
    const int tid = threadIdx.x;
    const int tm = (tid >> 4) << 2;
    const int tn = (tid & 15) << 2;
    const int lr = tid >> 2;
    const int lc = (tid & 3) << 2;
    float acc[4][4];
#pragma unroll
    for (int r = 0; r < 4; r++)
#pragma unroll
        for (int c = 0; c < 4; c++) acc[r][c] = 0.f;

    const float* Ap = A + (size_t)(bm + lr) * K + lc;
    const float* Bp = B + (size_t)(bn + lr) * K + lc;
    for (int k0 = 0; k0 < K; k0 += 16) {
        float4 a4 = *(const float4*)(Ap + k0);
        float4 b4 = *(const float4*)(Bp + k0);
        As[lc + 0][lr] = a4.x; As[lc + 1][lr] = a4.y;
        As[lc + 2][lr] = a4.z; As[lc + 3][lr] = a4.w;
        Bs[lc + 0][lr] = b4.x; Bs[lc + 1][lr] = b4.y;
        Bs[lc + 2][lr] = b4.z; Bs[lc + 3][lr] = b4.w;
        __syncthreads();
#pragma unroll
        for (int kk = 0; kk < 16; kk++) {
            float4 av = *(const float4*)&As[kk][tm];
            float4 bv = *(const float4*)&Bs[kk][tn];
            float a[4] = {av.x, av.y, av.z, av.w};
            float b[4] = {bv.x, bv.y, bv.z, bv.w};
#pragma unroll
            for (int r = 0; r < 4; r++)
#pragma unroll
                for (int c = 0; c < 4; c++)
                    acc[r][c] = fmaf(a[r], b[c], acc[r][c]);
        }
        __syncthreads();
    }
#pragma unroll
    for (int r = 0; r < 4; r++) {
        int row = bm + tm + r;
#pragma unroll
        for (int c = 0; c < 4; c++) {
            int col = bn + tn + c;
            float v = acc[r][c];
            if (bias) v += bias[col];
            if (relu) v = fmaxf(v, 0.f);
            C[(size_t)row * N + col] = v;
        }
    }
}

// ---------------- split-K fp32 GEMM, Cpart[z] = A[:,chunk] @ B[chunk,:]  (NN) ----
__global__ __launch_bounds__(256) void gemm_nn_splitk(
    const float* __restrict__ A, const float* __restrict__ B,
    float* __restrict__ Cpart, int M, int N, int Ktot)
{
    __shared__ float As[16][64];
    __shared__ float Bs[16][64];
    const int bm = blockIdx.y * 64;
    const int bn = blockIdx.x * 64;
    const int tid = threadIdx.x;
    const int tm = (tid >> 4) << 2;
    const int tn = (tid & 15) << 2;
    const int lr = tid >> 2;
    const int lc = (tid & 3) << 2;
    const int br = tid >> 4;          // 0..15
    const int bc = (tid & 15) << 2;   // 0..60
    const int kchunk = Ktot / gridDim.z;
    const int kbeg = blockIdx.z * kchunk;
    const int kend = kbeg + kchunk;
    float acc[4][4];
#pragma unroll
    for (int r = 0; r < 4; r++)
#pragma unroll
        for (int c = 0; c < 4; c++) acc[r][c] = 0.f;

    for (int k0 = kbeg; k0 < kend; k0 += 16) {
        float4 a4 = *(const float4*)(A + (size_t)(bm + lr) * Ktot + k0 + lc);
        float4 b4 = *(const float4*)(B + (size_t)(k0 + br) * N + bn + bc);
        As[lc + 0][lr] = a4.x; As[lc + 1][lr] = a4.y;
        As[lc + 2][lr] = a4.z; As[lc + 3][lr] = a4.w;
        Bs[br][bc + 0] = b4.x; Bs[br][bc + 1] = b4.y;
        Bs[br][bc + 2] = b4.z; Bs[br][bc + 3] = b4.w;
        __syncthreads();
#pragma unroll
        for (int kk = 0; kk < 16; kk++) {
            float4 av = *(const float4*)&As[kk][tm];
            float4 bv = *(const float4*)&Bs[kk][tn];
            float a[4] = {av.x, av.y, av.z, av.w};
            float b[4] = {bv.x, bv.y, bv.z, bv.w};
#pragma unroll
            for (int r = 0; r < 4; r++)
#pragma unroll
                for (int c = 0; c < 4; c++)
                    acc[r][c] = fmaf(a[r], b[c], acc[r][c]);
        }
        __syncthreads();
    }
    float* Cp = Cpart + (size_t)blockIdx.z * M * N;
#pragma unroll
    for (int r = 0; r < 4; r++)
#pragma unroll
        for (int c = 0; c < 4; c++)
            Cp[(size_t)(bm + tm + r) * N + bn + tn + c] = acc[r][c];
}

// ---------------- per-row: max, top-2(+idx), then P=exp(x-c) in place, E=sum ----
__global__ __launch_bounds__(256) void rowstat()
{
    const int i = blockIdx.x;
    const int t = threadIdx.x;
    float* row = g_Sb + (size_t)i * SLOTS;

    float v1 = NEG_INF; int i1 = -1;
    float v2 = NEG_INF; int i2 = -1;
    for (int s = t; s < SLOTS; s += 256) {
        float v = row[s];
        if (v > v1) { v2 = v1; i2 = i1; v1 = v; i1 = s; }
        else if (v > v2) { v2 = v; i2 = s; }
    }
    __shared__ float sv1[256], sv2[256];
    __shared__ int   si1[256], si2[256];
    sv1[t] = v1; si1[t] = i1; sv2[t] = v2; si2[t] = i2;
    __syncthreads();
    for (int off = 128; off > 0; off >>= 1) {
        if (t < off) {
            float b1 = sv1[t + off], b2 = sv2[t + off];
            int bi1 = si1[t + off], bi2 = si2[t + off];
            float a1 = sv1[t], a2 = sv2[t];
            int ai1 = si1[t], ai2 = si2[t];
            float n1, n2; int ni1, ni2;
            if (b1 > a1 || (b1 == a1 && bi1 < ai1)) {
                n1 = b1; ni1 = bi1;
                if (a1 > b2 || (a1 == b2 && ai1 < bi2)) { n2 = a1; ni2 = ai1; }
                else { n2 = b2; ni2 = bi2; }
            } else {
                n1 = a1; ni1 = ai1;
                if (b1 > a2 || (b1 == a2 && bi1 < ai2)) { n2 = b1; ni2 = bi1; }
                else { n2 = a2; ni2 = ai2; }
            }
            sv1[t] = n1; si1[t] = ni1; sv2[t] = n2; si2[t] = ni2;
        }
        __syncthreads();
    }
    __shared__ float cmax;
    if (t == 0) {
        cmax = sv1[0];
        g_c[i] = sv1[0];
        g_t1v[i] = sv1[0]; g_t1i[i] = si1[0];
        g_t2v[i] = sv2[0]; g_t2i[i] = si2[0];
    }
    __syncthreads();
    const float cm = cmax;
    float sum = 0.f;
    for (int s = t; s < SLOTS; s += 256) {
        float p = __expf(row[s] - cm);
        row[s] = p;
        sum += p;
    }
    sv1[t] = sum;
    __syncthreads();
    for (int off = 128; off > 0; off >>= 1) {
        if (t < off) sv1[t] += sv1[t + off];
        __syncthreads();
    }
    if (t == 0) g_E[i] = sv1[0];
}

// ---------------- sequential slot-chain resolution (single block) ----------------
__global__ __launch_bounds__(256) void seq_kernel()
{
    __shared__ unsigned bm_[SLOTS / 32];          // "ever written" bitmap
    __shared__ int slotS[256];
    __shared__ int deathS[256];
    __shared__ unsigned char liveF[256];
    __shared__ float rV[8]; __shared__ int rJ[8];
    __shared__ float s_wv; __shared__ int s_wj;
    __shared__ float s_bv; __shared__ int s_bs;
    __shared__ int s_fall, s_prev, s_slot;

    const int t = threadIdx.x;
    for (int w = t; w < SLOTS / 32; w += 256) bm_[w] = 0u;
    liveF[t] = 0; deathS[t] = 1 << 30; slotS[t] = -1;
    __syncthreads();

    for (int i = 0; i < BATCH; i++) {
        // --- candidate among live rewritten slots: max_j G[i,j] ---
        float v = NEG_INF; int jj = -1;
        if (t < i && liveF[t]) { v = g_G[i * BATCH + t]; jj = t; }
        for (int off = 16; off; off >>= 1) {
            float ov = __shfl_down_sync(0xffffffffu, v, off);
            int   oj = __shfl_down_sync(0xffffffffu, jj, off);
            bool take = false;
            if (oj >= 0) {
                if (jj < 0) take = true;
                else if (ov > v) take = true;
                else if (ov == v && slotS[oj] < slotS[jj]) take = true;
            }
            if (take) { v = ov; jj = oj; }
        }
        if ((t & 31) == 0) { rV[t >> 5] = v; rJ[t >> 5] = jj; }
        __syncthreads();
        if (t == 0) {
            float bv = rV[0]; int bj = rJ[0];
            for (int w = 1; w < 8; w++) {
                float ov = rV[w]; int oj = rJ[w];
                bool take = false;
                if (oj >= 0) {
                    if (bj < 0) take = true;
                    else if (ov > bv) take = true;
                    else if (ov == bv && slotS[oj] < slotS[bj]) take = true;
                }
                if (take) { bv = ov; bj = oj; }
            }
            s_wv = bv; s_wj = bj;
            // --- best untouched base-score candidate via top-2 ---
            s_fall = 0; s_prev = -1;
            int b1 = g_t1i[i];
            if (!((bm_[b1 >> 5] >> (b1 & 31)) & 1u)) { s_bs = b1; s_bv = g_t1v[i]; }
            else {
                int b2 = g_t2i[i];
                if (!((bm_[b2 >> 5] >> (b2 & 31)) & 1u)) { s_bs = b2; s_bv = g_t2v[i]; }
                else s_fall = 1;
            }
        }
        __syncthreads();
        if (s_fall) {
            // rare: both top-2 slots already written -> exact rescan of P row
            const float* Prow = g_Sb + (size_t)i * SLOTS;
            float fv = NEG_INF; int fs = -1;
            for (int s = t; s < SLOTS; s += 256) {
                if (!((bm_[s >> 5] >> (s & 31)) & 1u)) {
                    float p = Prow[s];
                    if (p > fv) { fv = p; fs = s; }
                }
            }
            for (int off = 16; off; off >>= 1) {
                float ov = __shfl_down_sync(0xffffffffu, fv, off);
                int   os = __shfl_down_sync(0xffffffffu, fs, off);
                if (os >= 0 && (fs < 0 || ov > fv || (ov == fv && os < fs))) { fv = ov; fs = os; }
            }
            if ((t & 31) == 0) { rV[t >> 5] = fv; rJ[t >> 5] = fs; }
            __syncthreads();
            if (t == 0) {
                float bv2 = rV[0]; int bs2 = rJ[0];
                for (int w = 1; w < 8; w++) {
                    if (rJ[w] >= 0 && (bs2 < 0 || rV[w] > bv2 ||
                        (rV[w] == bv2 && rJ[w] < bs2))) { bv2 = rV[w]; bs2 = rJ[w]; }
                }
                s_bs = bs2;
                s_bv = __logf(bv2) + g_c[i];  // back to raw-score units
            }
            __syncthreads();
        }
        if (t == 0) {
            float bestv = s_bv; int bests = s_bs;
            if (s_wj >= 0) {
                float wv = s_wv; int wslot = slotS[s_wj];
                if (wv > bestv || (wv == bestv && wslot < bests)) { bestv = wv; bests = wslot; }
            }
            s_slot = bests;
        }
        __syncthreads();
        if (t < i && liveF[t] && slotS[t] == s_slot) s_prev = t;  // at most one live writer
        __syncthreads();
        if (t == 0) {
            if (s_prev >= 0) { liveF[s_prev] = 0; deathS[s_prev] = i; }
            bm_[s_slot >> 5] |= (1u << (s_slot & 31));
            slotS[i] = s_slot; liveF[i] = 1;
            g_slot[i] = s_slot;
        }
        __syncthreads();
    }
    g_death[t] = deathS[t];
}

// ---------------- correction coefficient matrices ----------------
__global__ __launch_bounds__(256) void abuild()
{
    const int i = blockIdx.x;
    const int j = threadIdx.x;
    const bool live = (j < i) && (i <= g_death[j]);
    g_A1[i * BATCH + j] = live ? __expf(g_G[i * BATCH + j] - g_c[i]) : 0.f;
    g_A2[i * BATCH + j] = live ? g_Sb[(size_t)i * SLOTS + g_slot[j]] : 0.f;
}

// ---------------- copy S into merged left half ----------------
__global__ __launch_bounds__(512) void copyS(const float* __restrict__ S)
{
    const int i = blockIdx.x;
    const int t = threadIdx.x;
    g_merged[i * 2 * D + t] = S[(size_t)i * D + t];
}

// ---------------- read value: sum split-K partials + corrections, /Z ----------------
__global__ __launch_bounds__(512) void readfin(const float* __restrict__ mem_vals)
{
    const int i = blockIdx.x;
    const int t = threadIdx.x;
    __shared__ float a1[256], a2[256];
    __shared__ int sl[256];
    __shared__ float zsh;
    if (t < 256) {
        a1[t] = g_A1[i * BATCH + t];
        a2[t] = g_A2[i * BATCH + t];
        sl[t] = g_slot[t];
    }
    __syncthreads();
    if (t == 0) {
        float Z = g_E[i];
        for (int j = 0; j < BATCH; j++) Z += a1[j] - a2[j];
        zsh = Z;
    }
    __syncthreads();
    float acc = 0.f;
#pragma unroll
    for (int p = 0; p < NSPLIT; p++)
        acc += g_Rpart[((size_t)p * BATCH + i) * D + t];
    for (int j = 0; j < i; j++) {
        float w1 = a1[j], w2 = a2[j];
        if (w1 != 0.f || w2 != 0.f)
            acc += w1 * g_V[j * D + t] - w2 * mem_vals[(size_t)sl[j] * D + t];
    }
    g_merged[i * 2 * D + D + t] = acc / zsh;
}

// ---------------- host launch ----------------
extern "C" void kernel_launch(void* const* d_in, const int* in_sizes, int n_in,
                              void* d_out, int out_size)
{
    const float* S  = (const float*)d_in[0];
    const float* mk = (const float*)d_in[1];
    const float* mv = (const float*)d_in[2];
    const float* Wk = (const float*)d_in[3];
    const float* bk = (const float*)d_in[4];
    const float* Wv = (const float*)d_in[5];
    const float* bv = (const float*)d_in[6];
    const float* W1 = (const float*)d_in[7];
    const float* b1 = (const float*)d_in[8];
    const float* W2 = (const float*)d_in[9];
    const float* b2 = (const float*)d_in[10];
    float* out = (float*)d_out;
    (void)in_sizes; (void)n_in; (void)out_size;

    void *pK, *pV, *pG, *pSb, *pRp, *pM, *pH;
    cudaGetSymbolAddress(&pK,  g_K);
    cudaGetSymbolAddress(&pV,  g_V);
    cudaGetSymbolAddress(&pG,  g_G);
    cudaGetSymbolAddress(&pSb, g_Sb);
    cudaGetSymbolAddress(&pRp, g_Rpart);
    cudaGetSymbolAddress(&pM,  g_merged);
    cudaGetSymbolAddress(&pH,  g_hidden);

    const dim3 t256(256);

    // projections K = S Wk^T + bk,  V = S Wv^T + bv
    gemm_nt<<<dim3(D / 64, BATCH / 64), t256>>>(S, Wk, bk, (float*)pK, BATCH, D, D, 0);
    gemm_nt<<<dim3(D / 64, BATCH / 64), t256>>>(S, Wv, bv, (float*)pV, BATCH, D, D, 0);
    // Gram G = K K^T
    gemm_nt<<<dim3(BATCH / 64, BATCH / 64), t256>>>((const float*)pK, (const float*)pK,
                                                    nullptr, (float*)pG, BATCH, BATCH, D, 0);
    // base scores Sb = K @ mem_keys^T   [256 x 32768]
    gemm_nt<<<dim3(SLOTS / 64, BATCH / 64), t256>>>((const float*)pK, mk, nullptr,
                                                    (float*)pSb, BATCH, SLOTS, D, 0);
    // per-row max / top-2 / exp-in-place / sumexp
    rowstat<<<BATCH, 256>>>();
    // R partials = P @ mem_vals  (split-K)
    gemm_nn_splitk<<<dim3(D / 64, BATCH / 64, NSPLIT), t256>>>((const float*)pSb, mv,
                                                               (float*)pRp, BATCH, D, SLOTS);
    // sequential slot chain
    seq_kernel<<<1, 256>>>();
    // correction coefficients
    abuild<<<BATCH, 256>>>();
    // merged = [S | read_val]
    copyS<<<BATCH, 512>>>(S);
    readfin<<<BATCH, 512>>>(mv);
    // MLP
    gemm_nt<<<dim3(HID / 64, BATCH / 64), t256>>>((const float*)pM, W1, b1,
                                                  (float*)pH, BATCH, HID, 2 * D, 1);
    gemm_nt<<<dim3(D / 64, BATCH / 64), t256>>>((const float*)pH, W2, b2,
                                                out, BATCH, D, HID, 0);
}

// round 2
// speedup vs baseline: 1.2806x; 1.2806x over previous
#include <cuda_runtime.h>

#define BATCH 256
#define D     512
#define HID   2048
#define SLOTS 32768
#define NSPLIT 32

#define NEG_INF (-1e30f)

typedef unsigned long long ull;

// ---------------- device scratch (static allocation only) ----------------
__device__ float g_K[BATCH * D];
__device__ float g_V[BATCH * D];
__device__ float g_G[BATCH * BATCH];
__device__ float g_Gp[4 * BATCH * BATCH];
__device__ float g_Sb[(size_t)BATCH * SLOTS];   // raw scores, then P = exp(. - c) in-place
__device__ float g_c[BATCH];
__device__ float g_E[BATCH];
__device__ float g_t1v[BATCH];
__device__ float g_t2v[BATCH];
__device__ int   g_t1i[BATCH];
__device__ int   g_t2i[BATCH];
__device__ int   g_slot[BATCH];
__device__ int   g_death[BATCH];
__device__ float g_A1[BATCH * BATCH];
__device__ float g_A2[BATCH * BATCH];
__device__ float g_Rpart[(size_t)NSPLIT * BATCH * D];
__device__ float g_merged[BATCH * 2 * D];
__device__ float g_hidden[BATCH * HID];
__device__ float g_P2[4 * BATCH * D];

// ---------------- f32x2 packed helpers ----------------
__device__ __forceinline__ void fma2(ull& d, ull a, ull b) {
    asm("fma.rn.f32x2 %0, %1, %2, %0;" : "+l"(d) : "l"(a), "l"(b));
}
__device__ __forceinline__ ull dup2(float x) {
    ull r; asm("mov.b64 %0, {%1, %1};" : "=l"(r) : "f"(x)); return r;
}
__device__ __forceinline__ ull pk2(float lo, float hi) {
    ull r; asm("mov.b64 %0, {%1, %2};" : "=l"(r) : "f"(lo), "f"(hi)); return r;
}
__device__ __forceinline__ void upk2(ull v, float& lo, float& hi) {
    asm("mov.b64 {%0, %1}, %2;" : "=f"(lo), "=f"(hi) : "l"(v));
}

// =======================================================================
// 128x128x16 NT GEMM, 8x8 microtile, f32x2 packed FMA, double-buffered.
// C[M,N] = A[M,K] @ B[N,K]^T   (no bias/relu; M%128==0, N%128==0, K%16==0)
// =======================================================================
__global__ __launch_bounds__(256) void gemm_nt128(
    const float* __restrict__ A, const float* __restrict__ B,
    float* __restrict__ C, int M, int N, int K)
{
    __shared__ float As[2][16][132];
    __shared__ float Bs[2][16][132];
    const int bm = blockIdx.y * 128, bn = blockIdx.x * 128;
    const int tid = threadIdx.x;
    const int tm = (tid >> 4) << 3, tn = (tid & 15) << 3;
    const int lr = tid >> 2, lc = (tid & 3) << 2;

    const float* Ap0 = A + (size_t)(bm + lr) * K + lc;
    const float* Ap1 = A + (size_t)(bm + lr + 64) * K + lc;
    const float* Bp0 = B + (size_t)(bn + lr) * K + lc;
    const float* Bp1 = B + (size_t)(bn + lr + 64) * K + lc;

    ull acc[8][4];
#pragma unroll
    for (int r = 0; r < 8; r++)
#pragma unroll
        for (int c = 0; c < 4; c++) acc[r][c] = 0ull;

    float4 ra0 = *(const float4*)Ap0;
    float4 ra1 = *(const float4*)Ap1;
    float4 rb0 = *(const float4*)Bp0;
    float4 rb1 = *(const float4*)Bp1;

    const int nt = K >> 4;

#define NT_STS(b)                                                              \
    As[b][lc + 0][lr] = ra0.x; As[b][lc + 1][lr] = ra0.y;                      \
    As[b][lc + 2][lr] = ra0.z; As[b][lc + 3][lr] = ra0.w;                      \
    As[b][lc + 0][lr + 64] = ra1.x; As[b][lc + 1][lr + 64] = ra1.y;            \
    As[b][lc + 2][lr + 64] = ra1.z; As[b][lc + 3][lr + 64] = ra1.w;            \
    Bs[b][lc + 0][lr] = rb0.x; Bs[b][lc + 1][lr] = rb0.y;                      \
    Bs[b][lc + 2][lr] = rb0.z; Bs[b][lc + 3][lr] = rb0.w;                      \
    Bs[b][lc + 0][lr + 64] = rb1.x; Bs[b][lc + 1][lr + 64] = rb1.y;            \
    Bs[b][lc + 2][lr + 64] = rb1.z; Bs[b][lc + 3][lr + 64] = rb1.w;

    NT_STS(0)
    __syncthreads();

    for (int t = 0; t < nt; t++) {
        const int cur = t & 1;
        if (t + 1 < nt) {
            const int ko = (t + 1) << 4;
            ra0 = *(const float4*)(Ap0 + ko);
            ra1 = *(const float4*)(Ap1 + ko);
            rb0 = *(const float4*)(Bp0 + ko);
            rb1 = *(const float4*)(Bp1 + ko);
        }
#pragma unroll
        for (int kk = 0; kk < 16; kk++) {
            float4 a0 = *(const float4*)&As[cur][kk][tm];
            float4 a1 = *(const float4*)&As[cur][kk][tm + 4];
            float4 b0 = *(const float4*)&Bs[cur][kk][tn];
            float4 b1 = *(const float4*)&Bs[cur][kk][tn + 4];
            ull bb0 = pk2(b0.x, b0.y), bb1 = pk2(b0.z, b0.w);
            ull bb2 = pk2(b1.x, b1.y), bb3 = pk2(b1.z, b1.w);
            float av[8] = {a0.x, a0.y, a0.z, a0.w, a1.x, a1.y, a1.z, a1.w};
#pragma unroll
            for (int r = 0; r < 8; r++) {
                ull aa = dup2(av[r]);
                fma2(acc[r][0], aa, bb0); fma2(acc[r][1], aa, bb1);
                fma2(acc[r][2], aa, bb2); fma2(acc[r][3], aa, bb3);
            }
        }
        if (t + 1 < nt) {
            const int nb = 1 - cur;
            NT_STS(nb)
        }
        __syncthreads();
    }
#undef NT_STS

#pragma unroll
    for (int r = 0; r < 8; r++) {
        const size_t row = bm + tm + r;
        float4 o0, o1;
        upk2(acc[r][0], o0.x, o0.y); upk2(acc[r][1], o0.z, o0.w);
        upk2(acc[r][2], o1.x, o1.y); upk2(acc[r][3], o1.z, o1.w);
        *(float4*)&C[row * N + bn + tn] = o0;
        *(float4*)&C[row * N + bn + tn + 4] = o1;
    }
}

// =======================================================================
// 128x128x16 NN split-K GEMM (f32x2), Cpart[z] = A[:,chunk] @ B[chunk,:]
// =======================================================================
__global__ __launch_bounds__(256) void gemm_nn128_splitk(
    const float* __restrict__ A, const float* __restrict__ B,
    float* __restrict__ Cpart, int M, int N, int Ktot)
{
    __shared__ float As[2][16][132];
    __shared__ float Bs[2][16][132];
    const int bm = blockIdx.y * 128, bn = blockIdx.x * 128;
    const int tid = threadIdx.x;
    const int tm = (tid >> 4) << 3, tn = (tid & 15) << 3;
    const int lr = tid >> 2, lc = (tid & 3) << 2;
    const int brow = tid >> 5, bcol = (tid & 31) << 2;
    const int chunk = Ktot / gridDim.z;
    const int kbeg = blockIdx.z * chunk;
    const int nt = chunk >> 4;

    const float* Ap0 = A + (size_t)(bm + lr) * Ktot + kbeg + lc;
    const float* Ap1 = A + (size_t)(bm + lr + 64) * Ktot + kbeg + lc;
    const float* Bp0 = B + (size_t)(kbeg + brow) * N + bn + bcol;
    const float* Bp1 = B + (size_t)(kbeg + brow + 8) * N + bn + bcol;

    ull acc[8][4];
#pragma unroll
    for (int r = 0; r < 8; r++)
#pragma unroll
        for (int c = 0; c < 4; c++) acc[r][c] = 0ull;

    float4 ra0 = *(const float4*)Ap0;
    float4 ra1 = *(const float4*)Ap1;
    float4 rb0 = *(const float4*)Bp0;
    float4 rb1 = *(const float4*)Bp1;

#define NN_STS(b)                                                              \
    As[b][lc + 0][lr] = ra0.x; As[b][lc + 1][lr] = ra0.y;                      \
    As[b][lc + 2][lr] = ra0.z; As[b][lc + 3][lr] = ra0.w;                      \
    As[b][lc + 0][lr + 64] = ra1.x; As[b][lc + 1][lr + 64] = ra1.y;            \
    As[b][lc + 2][lr + 64] = ra1.z; As[b][lc + 3][lr + 64] = ra1.w;            \
    *(float4*)&Bs[b][brow][bcol] = rb0;                                        \
    *(float4*)&Bs[b][brow + 8][bcol] = rb1;

    NN_STS(0)
    __syncthreads();

    for (int t = 0; t < nt; t++) {
        const int cur = t & 1;
        if (t + 1 < nt) {
            const int ko = (t + 1) << 4;
            ra0 = *(const float4*)(Ap0 + ko);
            ra1 = *(const float4*)(Ap1 + ko);
            rb0 = *(const float4*)(Bp0 + (size_t)ko * N);
            rb1 = *(const float4*)(Bp1 + (size_t)ko * N);
        }
#pragma unroll
        for (int kk = 0; kk < 16; kk++) {
            float4 a0 = *(const float4*)&As[cur][kk][tm];
            float4 a1 = *(const float4*)&As[cur][kk][tm + 4];
            float4 b0 = *(const float4*)&Bs[cur][kk][tn];
            float4 b1 = *(const float4*)&Bs[cur][kk][tn + 4];
            ull bb0 = pk2(b0.x, b0.y), bb1 = pk2(b0.z, b0.w);
            ull bb2 = pk2(b1.x, b1.y), bb3 = pk2(b1.z, b1.w);
            float av[8] = {a0.x, a0.y, a0.z, a0.w, a1.x, a1.y, a1.z, a1.w};
#pragma unroll
            for (int r = 0; r < 8; r++) {
                ull aa = dup2(av[r]);
                fma2(acc[r][0], aa, bb0); fma2(acc[r][1], aa, bb1);
                fma2(acc[r][2], aa, bb2); fma2(acc[r][3], aa, bb3);
            }
        }
        if (t + 1 < nt) {
            const int nb = 1 - cur;
            NN_STS(nb)
        }
        __syncthreads();
    }
#undef NN_STS

    float* Cp = Cpart + (size_t)blockIdx.z * M * N;
#pragma unroll
    for (int r = 0; r < 8; r++) {
        const size_t row = bm + tm + r;
        float4 o0, o1;
        upk2(acc[r][0], o0.x, o0.y); upk2(acc[r][1], o0.z, o0.w);
        upk2(acc[r][2], o1.x, o1.y); upk2(acc[r][3], o1.z, o1.w);
        *(float4*)&Cp[row * N + bn + tn] = o0;
        *(float4*)&Cp[row * N + bn + tn + 4] = o1;
    }
}

// =======================================================================
// 64x64 NT GEMM body (4x4 microtile), used by proj / mlp1 / splitk64
// =======================================================================
__device__ __forceinline__ void gemm64_body(
    const float* __restrict__ A, const float* __restrict__ B,
    const float* __restrict__ bias, float* __restrict__ C,
    int M, int N, int K, int kbeg, int kend, int relu)
{
    __shared__ float As[16][64];
    __shared__ float Bs[16][64];
    const int bm = blockIdx.y * 64;
    const int bn = blockIdx.x * 64;
    const int tid = threadIdx.x;
    const int tm = (tid >> 4) << 2;
    const int tn = (tid & 15) << 2;
    const int lr = tid >> 2;
    const int lc = (tid & 3) << 2;
    float acc[4][4];
#pragma unroll
    for (int r = 0; r < 4; r++)
#pragma unroll
        for (int c = 0; c < 4; c++) acc[r][c] = 0.f;

    const float* Ap = A + (size_t)(bm + lr) * K + lc;
    const float* Bp = B + (size_t)(bn + lr) * K + lc;
    for (int k0 = kbeg; k0 < kend; k0 += 16) {
        float4 a4 = *(const float4*)(Ap + k0);
        float4 b4 = *(const float4*)(Bp + k0);
        As[lc + 0][lr] = a4.x; As[lc + 1][lr] = a4.y;
        As[lc + 2][lr] = a4.z; As[lc + 3][lr] = a4.w;
        Bs[lc + 0][lr] = b4.x; Bs[lc + 1][lr] = b4.y;
        Bs[lc + 2][lr] = b4.z; Bs[lc + 3][lr] = b4.w;
        __syncthreads();
#pragma unroll
        for (int kk = 0; kk < 16; kk++) {
            float4 av = *(const float4*)&As[kk][tm];
            float4 bv = *(const float4*)&Bs[kk][tn];
            float a[4] = {av.x, av.y, av.z, av.w};
            float b[4] = {bv.x, bv.y, bv.z, bv.w};
#pragma unroll
            for (int r = 0; r < 4; r++)
#pragma unroll
                for (int c = 0; c < 4; c++)
                    acc[r][c] = fmaf(a[r], b[c], acc[r][c]);
        }
        __syncthreads();
    }
#pragma unroll
    for (int r = 0; r < 4; r++) {
        int row = bm + tm + r;
#pragma unroll
        for (int c = 0; c < 4; c++) {
            int col = bn + tn + c;
            float v = acc[r][c];
            if (bias) v += bias[col];
            if (relu) v = fmaxf(v, 0.f);
            C[(size_t)row * N + col] = v;
        }
    }
}

// K and V projections fused across gridDim.z
__global__ __launch_bounds__(256) void proj_kernel(
    const float* __restrict__ S,
    const float* __restrict__ Wk, const float* __restrict__ bk,
    const float* __restrict__ Wv, const float* __restrict__ bv)
{
    if (blockIdx.z == 0)
        gemm64_body(S, Wk, bk, g_K, BATCH, D, D, 0, D, 0);
    else
        gemm64_body(S, Wv, bv, g_V, BATCH, D, D, 0, D, 0);
}

__global__ __launch_bounds__(256) void gemm_nt64(
    const float* __restrict__ A, const float* __restrict__ B,
    const float* __restrict__ bias, float* __restrict__ C,
    int M, int N, int K, int relu)
{
    gemm64_body(A, B, bias, C, M, N, K, 0, K, relu);
}

__global__ __launch_bounds__(256) void gemm_nt64_splitk(
    const float* __restrict__ A, const float* __restrict__ B,
    float* __restrict__ Cpart, int M, int N, int K)
{
    const int chunk = K / gridDim.z;
    const int kbeg = blockIdx.z * chunk;
    gemm64_body(A, B, nullptr, Cpart + (size_t)blockIdx.z * M * N,
                M, N, K, kbeg, kbeg + chunk, 0);
}

// reduce partials (+ optional bias broadcast over columns)
__global__ __launch_bounds__(256) void reduce_add(
    const float* __restrict__ part, const float* __restrict__ bias,
    float* __restrict__ out, int total, int N, int nz)
{
    int idx = blockIdx.x * 256 + threadIdx.x;
    if (idx >= total) return;
    float s = bias ? bias[idx % N] : 0.f;
    for (int z = 0; z < nz; z++) s += part[(size_t)z * total + idx];
    out[idx] = s;
}

// ---------------- per-row: max, top-2(+idx), then P=exp(x-c) in place, E=sum ----
__global__ __launch_bounds__(256) void rowstat()
{
    const int i = blockIdx.x;
    const int t = threadIdx.x;
    float* row = g_Sb + (size_t)i * SLOTS;

    float v1 = NEG_INF; int i1 = -1;
    float v2 = NEG_INF; int i2 = -1;
    for (int s = t; s < SLOTS; s += 256) {
        float v = row[s];
        if (v > v1) { v2 = v1; i2 = i1; v1 = v; i1 = s; }
        else if (v > v2) { v2 = v; i2 = s; }
    }
    __shared__ float sv1[256], sv2[256];
    __shared__ int   si1[256], si2[256];
    sv1[t] = v1; si1[t] = i1; sv2[t] = v2; si2[t] = i2;
    __syncthreads();
    for (int off = 128; off > 0; off >>= 1) {
        if (t < off) {
            float b1 = sv1[t + off], b2 = sv2[t + off];
            int bi1 = si1[t + off], bi2 = si2[t + off];
            float a1 = sv1[t], a2 = sv2[t];
            int ai1 = si1[t], ai2 = si2[t];
            float n1, n2; int ni1, ni2;
            if (b1 > a1 || (b1 == a1 && bi1 < ai1)) {
                n1 = b1; ni1 = bi1;
                if (a1 > b2 || (a1 == b2 && ai1 < bi2)) { n2 = a1; ni2 = ai1; }
                else { n2 = b2; ni2 = bi2; }
            } else {
                n1 = a1; ni1 = ai1;
                if (b1 > a2 || (b1 == a2 && bi1 < ai2)) { n2 = b1; ni2 = bi1; }
                else { n2 = a2; ni2 = ai2; }
            }
            sv1[t] = n1; si1[t] = ni1; sv2[t] = n2; si2[t] = ni2;
        }
        __syncthreads();
    }
    __shared__ float cmax;
    if (t == 0) {
        cmax = sv1[0];
        g_c[i] = sv1[0];
        g_t1v[i] = sv1[0]; g_t1i[i] = si1[0];
        g_t2v[i] = sv2[0]; g_t2i[i] = si2[0];
    }
    __syncthreads();
    const float cm = cmax;
    float sum = 0.f;
    for (int s = t; s < SLOTS; s += 256) {
        float p = __expf(row[s] - cm);
        row[s] = p;
        sum += p;
    }
    sv1[t] = sum;
    __syncthreads();
    for (int off = 128; off > 0; off >>= 1) {
        if (t < off) sv1[t] += sv1[t + off];
        __syncthreads();
    }
    if (t == 0) g_E[i] = sv1[0];
}

// ---------------- sequential slot-chain resolution (single block) ----------------
__global__ __launch_bounds__(256) void seq_kernel()
{
    __shared__ unsigned bm_[SLOTS / 32];          // "ever written" bitmap
    __shared__ int slotS[256];
    __shared__ int deathS[256];
    __shared__ unsigned char liveF[256];
    __shared__ float rV[8]; __shared__ int rJ[8];
    __shared__ float s_wv; __shared__ int s_wj;
    __shared__ float s_bv; __shared__ int s_bs;
    __shared__ int s_fall, s_prev, s_slot;

    const int t = threadIdx.x;
    for (int w = t; w < SLOTS / 32; w += 256) bm_[w] = 0u;
    liveF[t] = 0; deathS[t] = 1 << 30; slotS[t] = -1;
    __syncthreads();

    for (int i = 0; i < BATCH; i++) {
        float v = NEG_INF; int jj = -1;
        if (t < i && liveF[t]) { v = g_G[i * BATCH + t]; jj = t; }
        for (int off = 16; off; off >>= 1) {
            float ov = __shfl_down_sync(0xffffffffu, v, off);
            int   oj = __shfl_down_sync(0xffffffffu, jj, off);
            bool take = false;
            if (oj >= 0) {
                if (jj < 0) take = true;
                else if (ov > v) take = true;
                else if (ov == v && slotS[oj] < slotS[jj]) take = true;
            }
            if (take) { v = ov; jj = oj; }
        }
        if ((t & 31) == 0) { rV[t >> 5] = v; rJ[t >> 5] = jj; }
        __syncthreads();
        if (t == 0) {
            float bv = rV[0]; int bj = rJ[0];
            for (int w = 1; w < 8; w++) {
                float ov = rV[w]; int oj = rJ[w];
                bool take = false;
                if (oj >= 0) {
                    if (bj < 0) take = true;
                    else if (ov > bv) take = true;
                    else if (ov == bv && slotS[oj] < slotS[bj]) take = true;
                }
                if (take) { bv = ov; bj = oj; }
            }
            s_wv = bv; s_wj = bj;
            s_fall = 0; s_prev = -1;
            int b1 = g_t1i[i];
            if (!((bm_[b1 >> 5] >> (b1 & 31)) & 1u)) { s_bs = b1; s_bv = g_t1v[i]; }
            else {
                int b2 = g_t2i[i];
                if (!((bm_[b2 >> 5] >> (b2 & 31)) & 1u)) { s_bs = b2; s_bv = g_t2v[i]; }
                else s_fall = 1;
            }
        }
        __syncthreads();
        if (s_fall) {
            const float* Prow = g_Sb + (size_t)i * SLOTS;
            float fv = NEG_INF; int fs = -1;
            for (int s = t; s < SLOTS; s += 256) {
                if (!((bm_[s >> 5] >> (s & 31)) & 1u)) {
                    float p = Prow[s];
                    if (p > fv) { fv = p; fs = s; }
                }
            }
            for (int off = 16; off; off >>= 1) {
                float ov = __shfl_down_sync(0xffffffffu, fv, off);
                int   os = __shfl_down_sync(0xffffffffu, fs, off);
                if (os >= 0 && (fs < 0 || ov > fv || (ov == fv && os < fs))) { fv = ov; fs = os; }
            }
            if ((t & 31) == 0) { rV[t >> 5] = fv; rJ[t >> 5] = fs; }
            __syncthreads();
            if (t == 0) {
                float bv2 = rV[0]; int bs2 = rJ[0];
                for (int w = 1; w < 8; w++) {
                    if (rJ[w] >= 0 && (bs2 < 0 || rV[w] > bv2 ||
                        (rV[w] == bv2 && rJ[w] < bs2))) { bv2 = rV[w]; bs2 = rJ[w]; }
                }
                s_bs = bs2;
                s_bv = __logf(bv2) + g_c[i];
            }
            __syncthreads();
        }
        if (t == 0) {
            float bestv = s_bv; int bests = s_bs;
            if (s_wj >= 0) {
                float wv = s_wv; int wslot = slotS[s_wj];
                if (wv > bestv || (wv == bestv && wslot < bests)) { bestv = wv; bests = wslot; }
            }
            s_slot = bests;
        }
        __syncthreads();
        if (t < i && liveF[t] && slotS[t] == s_slot) s_prev = t;
        __syncthreads();
        if (t == 0) {
            if (s_prev >= 0) { liveF[s_prev] = 0; deathS[s_prev] = i; }
            bm_[s_slot >> 5] |= (1u << (s_slot & 31));
            slotS[i] = s_slot; liveF[i] = 1;
            g_slot[i] = s_slot;
        }
        __syncthreads();
    }
    g_death[t] = deathS[t];
}

// ---------------- correction coefficient matrices ----------------
__global__ __launch_bounds__(256) void abuild()
{
    const int i = blockIdx.x;
    const int j = threadIdx.x;
    const bool live = (j < i) && (i <= g_death[j]);
    g_A1[i * BATCH + j] = live ? __expf(g_G[i * BATCH + j] - g_c[i]) : 0.f;
    g_A2[i * BATCH + j] = live ? g_Sb[(size_t)i * SLOTS + g_slot[j]] : 0.f;
}

// ---------------- copy S into merged left half ----------------
__global__ __launch_bounds__(512) void copyS(const float* __restrict__ S)
{
    const int i = blockIdx.x;
    const int t = threadIdx.x;
    g_merged[i * 2 * D + t] = S[(size_t)i * D + t];
}

// ---------------- read value: sum split-K partials + corrections, /Z ----------------
__global__ __launch_bounds__(512) void readfin(const float* __restrict__ mem_vals)
{
    const int i = blockIdx.x;
    const int t = threadIdx.x;
    __shared__ float a1[256], a2[256];
    __shared__ int sl[256];
    __shared__ float zsh;
    if (t < 256) {
        a1[t] = g_A1[i * BATCH + t];
        a2[t] = g_A2[i * BATCH + t];
        sl[t] = g_slot[t];
    }
    __syncthreads();
    if (t == 0) {
        float Z = g_E[i];
        for (int j = 0; j < BATCH; j++) Z += a1[j] - a2[j];
        zsh = Z;
    }
    __syncthreads();
    float acc = 0.f;
#pragma unroll
    for (int p = 0; p < NSPLIT; p++)
        acc += g_Rpart[((size_t)p * BATCH + i) * D + t];
    for (int j = 0; j < i; j++) {
        float w1 = a1[j], w2 = a2[j];
        if (w1 != 0.f || w2 != 0.f)
            acc += w1 * g_V[j * D + t] - w2 * mem_vals[(size_t)sl[j] * D + t];
    }
    g_merged[i * 2 * D + D + t] = acc / zsh;
}

// ---------------- host launch ----------------
extern "C" void kernel_launch(void* const* d_in, const int* in_sizes, int n_in,
                              void* d_out, int out_size)
{
    const float* S  = (const float*)d_in[0];
    const float* mk = (const float*)d_in[1];
    const float* mv = (const float*)d_in[2];
    const float* Wk = (const float*)d_in[3];
    const float* bk = (const float*)d_in[4];
    const float* Wv = (const float*)d_in[5];
    const float* bv = (const float*)d_in[6];
    const float* W1 = (const float*)d_in[7];
    const float* b1 = (const float*)d_in[8];
    const float* W2 = (const float*)d_in[9];
    const float* b2 = (const float*)d_in[10];
    float* out = (float*)d_out;
    (void)in_sizes; (void)n_in; (void)out_size;

    void *pK, *pSb, *pRp, *pM, *pH, *pG, *pGp, *pP2;
    cudaGetSymbolAddress(&pK,  g_K);
    cudaGetSymbolAddress(&pSb, g_Sb);
    cudaGetSymbolAddress(&pRp, g_Rpart);
    cudaGetSymbolAddress(&pM,  g_merged);
    cudaGetSymbolAddress(&pH,  g_hidden);
    cudaGetSymbolAddress(&pG,  g_G);
    cudaGetSymbolAddress(&pGp, g_Gp);
    cudaGetSymbolAddress(&pP2, g_P2);

    const dim3 t256(256);

    // K = S Wk^T + bk,  V = S Wv^T + bv  (fused over gridDim.z)
    proj_kernel<<<dim3(D / 64, BATCH / 64, 2), t256>>>(S, Wk, bk, Wv, bv);
    // Gram G = K K^T (split-K x4 + reduce)
    gemm_nt64_splitk<<<dim3(BATCH / 64, BATCH / 64, 4), t256>>>(
        (const float*)pK, (const float*)pK, (float*)pGp, BATCH, BATCH, D);
    reduce_add<<<(BATCH * BATCH) / 256, t256>>>(
        (const float*)pGp, nullptr, (float*)pG, BATCH * BATCH, BATCH, 4);
    // base scores Sb = K @ mem_keys^T  [256 x 32768]  (f32x2 128-tile)
    gemm_nt128<<<dim3(SLOTS / 128, BATCH / 128), t256>>>(
        (const float*)pK, mk, (float*)pSb, BATCH, SLOTS, D);
    // per-row max / top-2 / exp-in-place / sumexp
    rowstat<<<BATCH, 256>>>();
    // R partials = P @ mem_vals  (f32x2 128-tile, split-K x32)
    gemm_nn128_splitk<<<dim3(D / 128, BATCH / 128, NSPLIT), t256>>>(
        (const float*)pSb, mv, (float*)pRp, BATCH, D, SLOTS);
    // sequential slot chain
    seq_kernel<<<1, 256>>>();
    // correction coefficients
    abuild<<<BATCH, 256>>>();
    // merged = [S | read_val]
    copyS<<<BATCH, 512>>>(S);
    readfin<<<BATCH, 512>>>(mv);
    // MLP layer 1 (relu)
    gemm_nt64<<<dim3(HID / 64, BATCH / 64), t256>>>(
        (const float*)pM, W1, b1, (float*)pH, BATCH, HID, 2 * D, 1);
    // MLP layer 2 (split-K x4 + bias reduce)
    gemm_nt64_splitk<<<dim3(D / 64, BATCH / 64, 4), t256>>>(
        (const float*)pH, W2, (float*)pP2, BATCH, D, HID);
    reduce_add<<<(BATCH * D) / 256, t256>>>(
        (const float*)pP2, b2, out, BATCH * D, D, 4);
}